// round 15
// baseline (speedup 1.0000x reference)
#include <cuda_runtime.h>
#include <cuda_fp16.h>
#include <cstdint>

#define NN   2048
#define CDIM 256
#define MS   4          // m splits (blockIdx.y)
#define PAD  264        // fp16 elems per smem row; 528 B row stride
#define NTILES (NN / MS / 32)   // 16

__device__ float    g_Z[2][NN * CDIM];
__device__ __half   g_Zh[2][NN * CDIM];          // fp16 high part, ping-pong
__device__ float    g_part[MS][NN * CDIM];       // per m-split partials
__device__ unsigned g_maskbits[NN * (NN / 32)];  // word[n*64+mw], bit = m&31
__device__ int      g_ctr[NN / 32];              // per n-range completion counters

// smem layout (bytes)
#define OFF_ZN   0                               // Zn fp16: 32 x PAD
#define OFF_ZM   (32 * PAD * 2)                  // 16896; 2 buffers
#define ZMBUF    (32 * PAD * 2)                  // 16896
#define OFF_SUM  (OFF_ZM + 2 * ZMBUF)            // 50688; 4 warps x 16x33 floats
#define SUMW     528                             // 16*33 floats per warp
#define SM_TOTAL (OFF_SUM + 4 * SUMW * 4)        // 59136

__device__ __forceinline__ uint32_t smem_u32(const void* p) {
    uint32_t a;
    asm("{ .reg .u64 t; cvta.to.shared.u64 t, %1; cvt.u32.u64 %0, t; }" : "=r"(a) : "l"(p));
    return a;
}
__device__ __forceinline__ uint32_t packh(float x0, float x1) {
    __half2 hp = __floats2half2_rn(x0, x1);
    return *(uint32_t*)&hp;
}

#define LDSM4(r, a) asm volatile( \
    "ldmatrix.sync.aligned.m8n8.x4.shared.b16 {%0,%1,%2,%3}, [%4];" \
    : "=r"((r)[0]), "=r"((r)[1]), "=r"((r)[2]), "=r"((r)[3]) : "r"(a))
#define LDSM4T(r, a) asm volatile( \
    "ldmatrix.sync.aligned.m8n8.x4.trans.shared.b16 {%0,%1,%2,%3}, [%4];" \
    : "=r"((r)[0]), "=r"((r)[1]), "=r"((r)[2]), "=r"((r)[3]) : "r"(a))
#define MMA(d, a, b0, b1) asm volatile( \
    "mma.sync.aligned.m16n8k16.row.col.f32.f16.f16.f32 " \
    "{%0,%1,%2,%3}, {%4,%5,%6,%7}, {%8,%9}, {%0,%1,%2,%3};" \
    : "+f"((d)[0]), "+f"((d)[1]), "+f"((d)[2]), "+f"((d)[3]) \
    : "r"((a)[0]), "r"((a)[1]), "r"((a)[2]), "r"((a)[3]), "r"(b0), "r"(b1))

// ---------------- init counters ----------------
__global__ void init_kernel() {
    if (threadIdx.x < NN / 32) g_ctr[threadIdx.x] = 0;
}

// ---------------- pack adjacency bits [n][mword] ----------------
__global__ void pack_mask_kernel(const int* __restrict__ adj) {
    int wIdx = blockIdx.x * 256 + threadIdx.x;
    const int4* p = ((const int4*)adj) + (size_t)wIdx * 8;
    unsigned bits = 0;
#pragma unroll
    for (int j = 0; j < 8; j++) {
        int4 v = p[j];
        if (v.x > 0) bits |= 1u << (4 * j + 0);
        if (v.y > 0) bits |= 1u << (4 * j + 1);
        if (v.z > 0) bits |= 1u << (4 * j + 2);
        if (v.w > 0) bits |= 1u << (4 * j + 3);
    }
    g_maskbits[wIdx] = bits;
}

// ---------------- projection + per-channel L2 norm ----------------
__global__ void proj_kernel(const float* __restrict__ feat,
                            const float* __restrict__ W,
                            const float* __restrict__ b) {
    __shared__ float fs[128];
    int n = blockIdx.x, t = threadIdx.x;
    if (t < 128) fs[t] = feat[n * 128 + t];
    __syncthreads();
    int k = t >> 5, d = t & 31;
    const float* Wp = W + k * 4096 + d;
    float s = b[t];
#pragma unroll 16
    for (int i = 0; i < 128; i++) s = fmaf(fs[i], Wp[i * 32], s);
    float ss = s * s;
#pragma unroll
    for (int o = 16; o; o >>= 1) ss += __shfl_xor_sync(0xffffffffu, ss, o);
    float inv = 1.0f / fmaxf(sqrtf(ss), 1e-12f);
    float r = s * inv;
    g_Z[0][(size_t)n * CDIM + t] = r;
    g_Zh[0][(size_t)n * CDIM + t] = __float2half_rn(r);
}

// ---------------- fused iteration, channel-split warps ----------------
// block: 32 n x 512 m; 4 warps = 2 n-blocks(16) x 2 channel-groups(4ch); 3 blocks/SM
__global__ __launch_bounds__(128, 3) void iter_kernel(int cur, float* __restrict__ outp) {
    extern __shared__ char smem[];
    uint32_t sb = smem_u32(smem);
    const __half* __restrict__ Zh = g_Zh[cur];
    int t = threadIdx.x, w = t >> 5, lane = t & 31;
    int nb = w & 1, cg = w >> 1;
    int g = lane >> 2, tig = lane & 3;
    int n0 = blockIdx.x * 32, mbase = blockIdx.y * (NN / MS);

    // ---- fill Zn (32 x 256 fp16): pure uint4 copy ----
#pragma unroll
    for (int it = 0; it < 8; it++) {
        int idx = t + it * 128;
        int n = idx >> 5, c4 = idx & 31;
        uint4 v = ((const uint4*)(Zh + (size_t)(n0 + n) * CDIM))[c4];
        *(uint4*)(smem + OFF_ZN + n * (PAD * 2) + c4 * 16) = v;
    }
    // fill Zm tile 0 into buffer 0
#pragma unroll
    for (int it = 0; it < 8; it++) {
        int idx = t + it * 128;
        int m = idx >> 5, c4 = idx & 31;
        uint4 v = ((const uint4*)(Zh + (size_t)(mbase + m) * CDIM))[c4];
        *(uint4*)(smem + OFF_ZM + m * (PAD * 2) + c4 * 16) = v;
    }
    __syncthreads();

    uint32_t aoffA = (uint32_t)(((nb * 16 + (lane & 15)) * PAD + ((lane >> 4) << 3)) * 2);
    uint32_t boffA = (uint32_t)(((((lane >> 4) << 3) + (lane & 7)) * PAD +
                                 (((lane >> 3) & 1) << 3)) * 2);
    uint32_t boffT = (uint32_t)((((((lane >> 3) & 1) << 3) + (lane & 7)) * PAD +
                                 ((lane >> 4) << 3)) * 2);
    int nA = n0 + nb * 16 + g;
    // sums exchange addressing (stride-33 padded) — MUST include sb (smem base)!
    uint32_t mybase   = sb + (uint32_t)(OFF_SUM + w * SUMW * 4)       + (uint32_t)((g * 33 + 2 * tig) * 4);
    uint32_t peerbase = sb + (uint32_t)(OFF_SUM + (w ^ 2) * SUMW * 4) + (uint32_t)((g * 33 + 2 * tig) * 4);

    float C[4][4][4];
#pragma unroll
    for (int c = 0; c < 4; c++)
#pragma unroll
        for (int q = 0; q < 4; q++) { C[c][q][0] = C[c][q][1] = C[c][q][2] = C[c][q][3] = 0.f; }

    for (int mt = 0; mt < NTILES; mt++) {
        int m0 = mbase + mt * 32;
        uint32_t bufc = OFF_ZM + (uint32_t)(mt & 1) * ZMBUF;

        // ---- prefetch next Zm tile ----
        if (mt < NTILES - 1) {
            uint32_t bufn = OFF_ZM + (uint32_t)((mt + 1) & 1) * ZMBUF;
            int m1 = m0 + 32;
#pragma unroll
            for (int it = 0; it < 8; it++) {
                int idx = t + it * 128;
                int m = idx >> 5, c4 = idx & 31;
                uint4 v = ((const uint4*)(Zh + (size_t)(m1 + m) * CDIM))[c4];
                *(uint4*)(smem + bufn + m * (PAD * 2) + c4 * 16) = v;
            }
        }

        // ---- Phase A: S[c][j] = ZnH(16n) . ZmH(32m)^T for 4 channels ----
        float S[4][4][4];   // [c][m8-block j][frag]
#pragma unroll
        for (int c = 0; c < 4; c++)
#pragma unroll
            for (int j = 0; j < 4; j++) { S[c][j][0] = S[c][j][1] = S[c][j][2] = S[c][j][3] = 0.f; }
#pragma unroll
        for (int c = 0; c < 4; c++) {
            int ch = cg * 4 + c;
#pragma unroll
            for (int ks = 0; ks < 2; ks++) {
                uint32_t kb2 = (uint32_t)(ch * 32 + ks * 16) * 2;
                uint32_t aH[4];
                LDSM4(aH, sb + OFF_ZN + aoffA + kb2);
#pragma unroll
                for (int mb = 0; mb < 2; mb++) {
                    uint32_t bH[4];
                    LDSM4(bH, sb + bufc + boffA + (uint32_t)mb * (16 * PAD * 2) + kb2);
                    MMA(S[c][mb * 2 + 0], aH, bH[0], bH[1]);
                    MMA(S[c][mb * 2 + 1], aH, bH[2], bH[3]);
                }
            }
        }

        // ---- exp + my 4-channel partial sums ----
        float ps[4][4];
#pragma unroll
        for (int j = 0; j < 4; j++)
#pragma unroll
            for (int q = 0; q < 4; q++) ps[j][q] = 0.f;
#pragma unroll
        for (int c = 0; c < 4; c++)
#pragma unroll
            for (int j = 0; j < 4; j++)
#pragma unroll
                for (int q = 0; q < 4; q++) {
                    float e = __expf(S[c][j][q]);   // |s|<=1: safe
                    S[c][j][q] = e; ps[j][q] += e;
                }
        // publish partial sums
#pragma unroll
        for (int j = 0; j < 4; j++)
#pragma unroll
            for (int q = 0; q < 4; q++) {
                uint32_t off = mybase + (uint32_t)(((q >> 1) * 8 * 33 + j * 8 + (q & 1)) * 4);
                asm volatile("st.shared.f32 [%0], %1;" :: "r"(off), "f"(ps[j][q]) : "memory");
            }
        __syncthreads();

        // total sums + mask -> inv
        unsigned wA = g_maskbits[(size_t)nA * 64 + (m0 >> 5)];
        unsigned wB = g_maskbits[(size_t)(nA + 8) * 64 + (m0 >> 5)];
        float inv[4][4];
#pragma unroll
        for (int j = 0; j < 4; j++)
#pragma unroll
            for (int q = 0; q < 4; q++) {
                uint32_t off = peerbase + (uint32_t)(((q >> 1) * 8 * 33 + j * 8 + (q & 1)) * 4);
                float peer;
                asm volatile("ld.shared.f32 %0, [%1];" : "=f"(peer) : "r"(off));
                float tot = ps[j][q] + peer;
                int bitpos = j * 8 + 2 * tig + (q & 1);
                unsigned wd = (q >> 1) ? wB : wA;
                inv[j][q] = ((wd >> bitpos) & 1u) ? __fdividef(1.f, tot) : 0.f;
            }

        // att -> fp16 A-fragments (k = m within tile; kc = 16-k chunk)
        uint32_t attH[4][2][4];
#pragma unroll
        for (int c = 0; c < 4; c++)
#pragma unroll
            for (int kc = 0; kc < 2; kc++) {
                int j0 = kc * 2, j1 = kc * 2 + 1;
                attH[c][kc][0] = packh(S[c][j0][0] * inv[j0][0], S[c][j0][1] * inv[j0][1]);
                attH[c][kc][1] = packh(S[c][j0][2] * inv[j0][2], S[c][j0][3] * inv[j0][3]);
                attH[c][kc][2] = packh(S[c][j1][0] * inv[j1][0], S[c][j1][1] * inv[j1][1]);
                attH[c][kc][3] = packh(S[c][j1][2] * inv[j1][2], S[c][j1][3] * inv[j1][3]);
            }

        // ---- Phase B: C[c] += att . ZmH over full 32m, own 4 channels ----
#pragma unroll
        for (int c = 0; c < 4; c++) {
            int ch = cg * 4 + c;
            uint32_t d0 = (uint32_t)(ch * 32) * 2, d1 = (uint32_t)(ch * 32 + 16) * 2;
#pragma unroll
            for (int kc = 0; kc < 2; kc++) {
                uint32_t rowoff = (uint32_t)kc * (16 * PAD * 2);
                uint32_t bt0[4], bt1[4];
                LDSM4T(bt0, sb + bufc + boffT + rowoff + d0);
                LDSM4T(bt1, sb + bufc + boffT + rowoff + d1);
                MMA(C[c][0], attH[c][kc], bt0[0], bt0[1]);
                MMA(C[c][1], attH[c][kc], bt0[2], bt0[3]);
                MMA(C[c][2], attH[c][kc], bt1[0], bt1[1]);
                MMA(C[c][3], attH[c][kc], bt1[2], bt1[3]);
            }
        }
        __syncthreads();
    }

    // ---- write partials (each warp owns disjoint 16n x 128d region) ----
    {
        float* dst = g_part[blockIdx.y];
#pragma unroll
        for (int c = 0; c < 4; c++) {
            int ch = cg * 4 + c;
#pragma unroll
            for (int dj = 0; dj < 4; dj++) {
                int d = ch * 32 + dj * 8 + 2 * tig;
                *(float2*)&dst[(size_t)nA * CDIM + d]       = make_float2(C[c][dj][0], C[c][dj][1]);
                *(float2*)&dst[(size_t)(nA + 8) * CDIM + d] = make_float2(C[c][dj][2], C[c][dj][3]);
            }
        }
    }

    // ---- last m-split block for this n-range: residual + sum + per-channel L2 ----
    __syncthreads();
    __shared__ int s_last;
    if (t == 0) {
        __threadfence();
        int old = atomicAdd(&g_ctr[blockIdx.x], 1);
        s_last = ((old & (MS - 1)) == MS - 1);
    }
    __syncthreads();
    if (!s_last) return;
    __threadfence();

    const float* __restrict__ Zc = g_Z[cur];
    float*  __restrict__ Zn32 = g_Z[cur ^ 1];
    __half* __restrict__ Zh_n = g_Zh[cur ^ 1];
    for (int r = 0; r < 8; r++) {
        int n = n0 + w * 8 + r;
        size_t base = (size_t)n * CDIM;
        float4 v0 = *(const float4*)&Zc[base + lane * 4];
        float4 v1 = *(const float4*)&Zc[base + 128 + lane * 4];
#pragma unroll
        for (int s = 0; s < MS; s++) {
            float4 p0 = *(const float4*)&g_part[s][base + lane * 4];
            float4 p1 = *(const float4*)&g_part[s][base + 128 + lane * 4];
            v0.x += p0.x; v0.y += p0.y; v0.z += p0.z; v0.w += p0.w;
            v1.x += p1.x; v1.y += p1.y; v1.z += p1.z; v1.w += p1.w;
        }
        float ss0 = v0.x * v0.x + v0.y * v0.y + v0.z * v0.z + v0.w * v0.w;
        float ss1 = v1.x * v1.x + v1.y * v1.y + v1.z * v1.z + v1.w * v1.w;
#pragma unroll
        for (int o = 4; o; o >>= 1) {
            ss0 += __shfl_xor_sync(0xffffffffu, ss0, o);
            ss1 += __shfl_xor_sync(0xffffffffu, ss1, o);
        }
        float inv0 = 1.0f / fmaxf(sqrtf(ss0), 1e-12f);
        float inv1 = 1.0f / fmaxf(sqrtf(ss1), 1e-12f);
        v0.x *= inv0; v0.y *= inv0; v0.z *= inv0; v0.w *= inv0;
        v1.x *= inv1; v1.y *= inv1; v1.z *= inv1; v1.w *= inv1;
        if (outp) {
            *(float4*)&outp[base + lane * 4] = v0;
            *(float4*)&outp[base + 128 + lane * 4] = v1;
        } else {
            *(float4*)&Zn32[base + lane * 4] = v0;
            *(float4*)&Zn32[base + 128 + lane * 4] = v1;
            __half2* hd = (__half2*)&Zh_n[base];
            hd[lane * 2]          = __floats2half2_rn(v0.x, v0.y);
            hd[lane * 2 + 1]      = __floats2half2_rn(v0.z, v0.w);
            hd[64 + lane * 2]     = __floats2half2_rn(v1.x, v1.y);
            hd[64 + lane * 2 + 1] = __floats2half2_rn(v1.z, v1.w);
        }
    }
}

extern "C" void kernel_launch(void* const* d_in, const int* in_sizes, int n_in,
                              void* d_out, int out_size) {
    const int* adj = nullptr; const float* feat = nullptr;
    const float* W = nullptr; const float* b = nullptr;
    for (int i = 0; i < n_in; i++) {
        switch (in_sizes[i]) {
            case NN * NN:      adj  = (const int*)d_in[i];   break;
            case NN * 128:     feat = (const float*)d_in[i]; break;
            case 8 * 128 * 32: W    = (const float*)d_in[i]; break;
            case 256:          b    = (const float*)d_in[i]; break;
        }
    }
    float* out = (float*)d_out;

    cudaFuncSetAttribute(iter_kernel, cudaFuncAttributeMaxDynamicSharedMemorySize, SM_TOTAL);

    init_kernel<<<1, 64>>>();
    pack_mask_kernel<<<NN * (NN / 32) / 256, 256>>>(adj);
    proj_kernel<<<NN, 256>>>(feat, W, b);

    int cur = 0;
    for (int it = 0; it < 4; it++) {
        dim3 grid(NN / 32, MS);
        iter_kernel<<<grid, 128, SM_TOTAL>>>(cur, (it == 3) ? out : nullptr);
        cur ^= 1;
    }
}

// round 16
// speedup vs baseline: 1.6923x; 1.6923x over previous
#include <cuda_runtime.h>
#include <cuda_fp16.h>
#include <cstdint>

#define NN   2048
#define CDIM 256
#define MS   8          // m splits (blockIdx.y)
#define PAD  264        // fp16 elems per smem row (padded); 528 B row stride

__device__ float    g_Z[2][NN * CDIM];
__device__ __half   g_Zh[NN * CDIM];             // fp16 high part of current Z
__device__ __half   g_part[MS][NN * CDIM];       // per m-split partials (fp16)
__device__ unsigned g_maskbits[NN * (NN / 32)];  // word[n*64+mw], bit = m&31

// smem layout (bytes): block = 32n x 256m-tilechain
#define OFF_ZN   0                               // Zn fp16: 32 x PAD
#define OFF_ZM   (32 * PAD * 2)                  // 16896; 2 buffers
#define ZMBUF    (32 * PAD * 2)                  // 16896
#define SM_TOTAL (OFF_ZM + 2 * ZMBUF)            // 50688
#define CPAD     264                             // combine stride (floats)

__device__ __forceinline__ uint32_t smem_u32(const void* p) {
    uint32_t a;
    asm("{ .reg .u64 t; cvta.to.shared.u64 t, %1; cvt.u32.u64 %0, t; }" : "=r"(a) : "l"(p));
    return a;
}
__device__ __forceinline__ uint32_t packh(float x0, float x1) {
    __half2 hp = __floats2half2_rn(x0, x1);
    return *(uint32_t*)&hp;
}

#define LDSM4(r, a) asm volatile( \
    "ldmatrix.sync.aligned.m8n8.x4.shared.b16 {%0,%1,%2,%3}, [%4];" \
    : "=r"((r)[0]), "=r"((r)[1]), "=r"((r)[2]), "=r"((r)[3]) : "r"(a))
#define LDSM4T(r, a) asm volatile( \
    "ldmatrix.sync.aligned.m8n8.x4.trans.shared.b16 {%0,%1,%2,%3}, [%4];" \
    : "=r"((r)[0]), "=r"((r)[1]), "=r"((r)[2]), "=r"((r)[3]) : "r"(a))
#define MMA(d, a, b0, b1) asm volatile( \
    "mma.sync.aligned.m16n8k16.row.col.f32.f16.f16.f32 " \
    "{%0,%1,%2,%3}, {%4,%5,%6,%7}, {%8,%9}, {%0,%1,%2,%3};" \
    : "+f"((d)[0]), "+f"((d)[1]), "+f"((d)[2]), "+f"((d)[3]) \
    : "r"((a)[0]), "r"((a)[1]), "r"((a)[2]), "r"((a)[3]), "r"(b0), "r"(b1))

// ---------------- pack adjacency bits [n][mword] ----------------
__global__ void pack_mask_kernel(const int* __restrict__ adj) {
    int wIdx = blockIdx.x * 256 + threadIdx.x;
    const int4* p = ((const int4*)adj) + (size_t)wIdx * 8;
    unsigned bits = 0;
#pragma unroll
    for (int j = 0; j < 8; j++) {
        int4 v = p[j];
        if (v.x > 0) bits |= 1u << (4 * j + 0);
        if (v.y > 0) bits |= 1u << (4 * j + 1);
        if (v.z > 0) bits |= 1u << (4 * j + 2);
        if (v.w > 0) bits |= 1u << (4 * j + 3);
    }
    g_maskbits[wIdx] = bits;
}

// ---------------- projection + per-channel L2 norm (fp32 + fp16 out) ----------------
__global__ void proj_kernel(const float* __restrict__ feat,
                            const float* __restrict__ W,
                            const float* __restrict__ b) {
    __shared__ float fs[128];
    int n = blockIdx.x, t = threadIdx.x;
    if (t < 128) fs[t] = feat[n * 128 + t];
    __syncthreads();
    int k = t >> 5, d = t & 31;
    const float* Wp = W + k * 4096 + d;
    float s = b[t];
#pragma unroll 16
    for (int i = 0; i < 128; i++) s = fmaf(fs[i], Wp[i * 32], s);
    float ss = s * s;
#pragma unroll
    for (int o = 16; o; o >>= 1) ss += __shfl_xor_sync(0xffffffffu, ss, o);
    float inv = 1.0f / fmaxf(sqrtf(ss), 1e-12f);
    float r = s * inv;
    g_Z[0][(size_t)n * CDIM + t] = r;
    g_Zh[(size_t)n * CDIM + t] = __float2half_rn(r);
}

// ---------------- fused iteration (R11 structure) ----------------
// block: 32 n x 256 m; 4 warps = 2 n-blocks(16) x 2 m-halves(128); 2 blocks/SM
__global__ __launch_bounds__(128, 2) void iter_kernel(int unused) {
    extern __shared__ char smem[];
    uint32_t sb = smem_u32(smem);
    int t = threadIdx.x, w = t >> 5, lane = t & 31;
    int nb = w & 1, mh = w >> 1;
    int g = lane >> 2, tig = lane & 3;
    int n0 = blockIdx.x * 32, mbase = blockIdx.y * (NN / MS);

    // ---- fill Zn (32 x 256 fp16): pure uint4 copy ----
#pragma unroll
    for (int it = 0; it < 8; it++) {
        int idx = t + it * 128;
        int n = idx >> 5, c4 = idx & 31;
        uint4 v = ((const uint4*)(g_Zh + (size_t)(n0 + n) * CDIM))[c4];
        *(uint4*)(smem + OFF_ZN + n * (PAD * 2) + c4 * 16) = v;
    }
    // fill Zm tile 0 into buffer 0
#pragma unroll
    for (int it = 0; it < 8; it++) {
        int idx = t + it * 128;
        int m = idx >> 5, c4 = idx & 31;
        uint4 v = ((const uint4*)(g_Zh + (size_t)(mbase + m) * CDIM))[c4];
        *(uint4*)(smem + OFF_ZM + m * (PAD * 2) + c4 * 16) = v;
    }
    __syncthreads();

    uint32_t aoffA = (uint32_t)(((nb * 16 + (lane & 15)) * PAD + ((lane >> 4) << 3)) * 2);
    uint32_t boffA = (uint32_t)(((mh * 16 + ((lane >> 4) << 3) + (lane & 7)) * PAD +
                                 (((lane >> 3) & 1) << 3)) * 2);
    uint32_t boffT = (uint32_t)(((mh * 16 + (((lane >> 3) & 1) << 3) + (lane & 7)) * PAD +
                                 ((lane >> 4) << 3)) * 2);
    int nA = n0 + nb * 16 + g;

    float C[8][4][4];
#pragma unroll
    for (int c = 0; c < 8; c++)
#pragma unroll
        for (int q = 0; q < 4; q++) { C[c][q][0] = C[c][q][1] = C[c][q][2] = C[c][q][3] = 0.f; }

    for (int mt = 0; mt < 8; mt++) {
        int m0 = mbase + mt * 32;
        uint32_t bufc = OFF_ZM + (uint32_t)(mt & 1) * ZMBUF;

        // ---- prefetch next Zm tile (pure copy, overlaps compute) ----
        if (mt < 7) {
            uint32_t bufn = OFF_ZM + (uint32_t)((mt + 1) & 1) * ZMBUF;
            int m1 = m0 + 32;
#pragma unroll
            for (int it = 0; it < 8; it++) {
                int idx = t + it * 128;
                int m = idx >> 5, c4 = idx & 31;
                uint4 v = ((const uint4*)(g_Zh + (size_t)(m1 + m) * CDIM))[c4];
                *(uint4*)(smem + bufn + m * (PAD * 2) + c4 * 16) = v;
            }
        }

        // ---- Phase A: S = ZnH . ZmH^T (single fp16 term) ----
        float S[8][2][4];
#pragma unroll
        for (int c = 0; c < 8; c++)
#pragma unroll
            for (int ms = 0; ms < 2; ms++) { S[c][ms][0] = S[c][ms][1] = S[c][ms][2] = S[c][ms][3] = 0.f; }
#pragma unroll
        for (int ch = 0; ch < 8; ch++) {
#pragma unroll
            for (int ks = 0; ks < 2; ks++) {
                uint32_t kb2 = (uint32_t)(ch * 32 + ks * 16) * 2;
                uint32_t aH[4], bH[4];
                LDSM4(aH, sb + OFF_ZN + aoffA + kb2);
                LDSM4(bH, sb + bufc + boffA + kb2);
                MMA(S[ch][0], aH, bH[0], bH[1]);
                MMA(S[ch][1], aH, bH[2], bH[3]);
            }
        }

        // ---- softmax over channels (in-lane) ----
        float sum[2][4];
#pragma unroll
        for (int ms = 0; ms < 2; ms++)
#pragma unroll
            for (int q = 0; q < 4; q++) sum[ms][q] = 0.f;
#pragma unroll
        for (int ch = 0; ch < 8; ch++)
#pragma unroll
            for (int ms = 0; ms < 2; ms++)
#pragma unroll
                for (int q = 0; q < 4; q++) {
                    float e = __expf(S[ch][ms][q]);   // |s|<=1
                    S[ch][ms][q] = e; sum[ms][q] += e;
                }
        unsigned wA = g_maskbits[(size_t)nA * 64 + (m0 >> 5)];
        unsigned wB = g_maskbits[(size_t)(nA + 8) * 64 + (m0 >> 5)];
        float inv[2][4];
#pragma unroll
        for (int ms = 0; ms < 2; ms++)
#pragma unroll
            for (int q = 0; q < 4; q++) {
                int bitpos = mh * 16 + ms * 8 + 2 * tig + (q & 1);
                unsigned wd = (q >> 1) ? wB : wA;
                inv[ms][q] = ((wd >> bitpos) & 1u) ? __fdividef(1.f, sum[ms][q]) : 0.f;
            }
        uint32_t attH[8][4];
#pragma unroll
        for (int ch = 0; ch < 8; ch++)
#pragma unroll
            for (int ms = 0; ms < 2; ms++) {
                attH[ch][ms * 2]     = packh(S[ch][ms][0] * inv[ms][0], S[ch][ms][1] * inv[ms][1]);
                attH[ch][ms * 2 + 1] = packh(S[ch][ms][2] * inv[ms][2], S[ch][ms][3] * inv[ms][3]);
            }

        // ---- Phase B: C += attH . ZmH (single term) ----
#pragma unroll
        for (int ch = 0; ch < 8; ch++) {
            uint32_t d0 = (uint32_t)(ch * 32) * 2, d1 = (uint32_t)(ch * 32 + 16) * 2;
            uint32_t bh0[4], bh1[4];
            LDSM4T(bh0, sb + bufc + boffT + d0);
            LDSM4T(bh1, sb + bufc + boffT + d1);
            MMA(C[ch][0], attH[ch], bh0[0], bh0[1]);
            MMA(C[ch][1], attH[ch], bh0[2], bh0[3]);
            MMA(C[ch][2], attH[ch], bh1[0], bh1[1]);
            MMA(C[ch][3], attH[ch], bh1[2], bh1[3]);
        }
        __syncthreads();
    }

    // ---- combine m-halves in smem (overlays dead buffers), write fp16 g_part ----
    float* comb = (float*)smem;
    if (mh == 1) {
        int nl = nb * 16 + g;
#pragma unroll
        for (int ch = 0; ch < 8; ch++)
#pragma unroll
            for (int db = 0; db < 4; db++) {
                int d = ch * 32 + db * 8 + 2 * tig;
                *(float2*)&comb[(size_t)nl * CPAD + d]       = make_float2(C[ch][db][0], C[ch][db][1]);
                *(float2*)&comb[(size_t)(nl + 8) * CPAD + d] = make_float2(C[ch][db][2], C[ch][db][3]);
            }
    }
    __syncthreads();
    if (mh == 0) {
        int nl = nb * 16 + g;
        __half* dst = g_part[blockIdx.y];
#pragma unroll
        for (int ch = 0; ch < 8; ch++)
#pragma unroll
            for (int db = 0; db < 4; db++) {
                int d = ch * 32 + db * 8 + 2 * tig;
                float2 o0 = *(float2*)&comb[(size_t)nl * CPAD + d];
                float2 o1 = *(float2*)&comb[(size_t)(nl + 8) * CPAD + d];
                *(__half2*)&dst[(size_t)nA * CDIM + d] =
                    __floats2half2_rn(C[ch][db][0] + o0.x, C[ch][db][1] + o0.y);
                *(__half2*)&dst[(size_t)(nA + 8) * CDIM + d] =
                    __floats2half2_rn(C[ch][db][2] + o1.x, C[ch][db][3] + o1.y);
            }
    }
}

// ---------------- residual + sum 8 fp16 partials + per-channel L2 norm ----------------
__global__ void norm_kernel(int zi, int zo, float* __restrict__ outp) {
    int n = blockIdx.x, t = threadIdx.x;
    size_t i = (size_t)n * CDIM + t;
    float v = g_Z[zi][i];
#pragma unroll
    for (int s = 0; s < MS; s++) v += __half2float(g_part[s][i]);
    float ss = v * v;
#pragma unroll
    for (int o = 16; o; o >>= 1) ss += __shfl_xor_sync(0xffffffffu, ss, o);
    float r = v / fmaxf(sqrtf(ss), 1e-12f);
    if (outp) { outp[i] = r; }
    else {
        g_Z[zo][i] = r;
        g_Zh[i] = __float2half_rn(r);
    }
}

extern "C" void kernel_launch(void* const* d_in, const int* in_sizes, int n_in,
                              void* d_out, int out_size) {
    const int* adj = nullptr; const float* feat = nullptr;
    const float* W = nullptr; const float* b = nullptr;
    for (int i = 0; i < n_in; i++) {
        switch (in_sizes[i]) {
            case NN * NN:      adj  = (const int*)d_in[i];   break;
            case NN * 128:     feat = (const float*)d_in[i]; break;
            case 8 * 128 * 32: W    = (const float*)d_in[i]; break;
            case 256:          b    = (const float*)d_in[i]; break;
        }
    }
    float* out = (float*)d_out;

    cudaFuncSetAttribute(iter_kernel, cudaFuncAttributeMaxDynamicSharedMemorySize, SM_TOTAL);

    pack_mask_kernel<<<NN * (NN / 32) / 256, 256>>>(adj);
    proj_kernel<<<NN, 256>>>(feat, W, b);

    int cur = 0;
    for (int it = 0; it < 4; it++) {
        dim3 grid(NN / 32, MS);
        iter_kernel<<<grid, 128, SM_TOTAL>>>(0);
        norm_kernel<<<NN, 256>>>(cur, cur ^ 1, (it == 3) ? out : nullptr);
        cur ^= 1;
    }
}